// round 8
// baseline (speedup 1.0000x reference)
#include <cuda_runtime.h>
#include <math.h>

#define NN 50000
#define KK 16
#define EE 800000
#define BBATCH 1024
#define MAXM 48
#define FD 9
#define AD 10
#define HH 64
#define NEGINF (-1e9f)
#define NB_EMB 3126              // ceil((NN+1)/16)
#define NB_ELOG 3125             // EE/256

typedef unsigned long long u64;

__device__ __forceinline__ void ffma2(u64& o, u64 a, u64 w) {
    asm("fma.rn.f32x2 %0, %1, %2, %0;" : "+l"(o) : "l"(a), "l"(w));
}
__device__ __forceinline__ u64 pack2(float x) {
    u64 r;
    asm("mov.b64 %0, {%1, %1};" : "=l"(r) : "r"(__float_as_uint(x)));
    return r;
}
__device__ __forceinline__ float2 unpack2(u64 v) {
    float2 f;
    asm("mov.b64 {%0, %1}, %2;" : "=f"(f.x), "=f"(f.y) : "l"(v));
    return f;
}

// ---------------- scratch ------------------------------------------------------
__device__ float4 d_hp0v[(NN + 1) * 16];
__device__ float4 d_th1v[(NN + 1) * 16];   // hp1 @ Wg (row 0 = 0)
__device__ float4 d_tm1v[(NN + 1) * 16];   // hp1 @ Wm (row 0 = 0)
__device__ float4 d_hp2v[(NN + 1) * 16];
__device__ float d_gp0[NN + 1];
__device__ float d_gp1[NN + 1];
__device__ float d_gm1[NN + 1];
__device__ float d_elog[EE];
__device__ float4 d_accAv[NN * 16];
__device__ float d_accX16[NN * 16];
__device__ float4 d_p4[16];
__device__ float4 d_q4[16];
__device__ float d_qd[AD];
__device__ float d_c;
__device__ float d_wep[FD];      // We @ p
__device__ float d_c0;           // be . p
__device__ float4 d_M14[AD * 16];
__device__ float4 d_bm4[16];

// ---------------- constants -----------------------------------------------------
__global__ __launch_bounds__(256) void k_consts(const float* __restrict__ Wg,
                                                const float* __restrict__ Wm,
                                                const float* __restrict__ a,
                                                const float* __restrict__ Wd,
                                                const float* __restrict__ bd,
                                                const float* __restrict__ We,
                                                const float* __restrict__ be) {
    __shared__ float sp[HH], sq[HH];
    int t = threadIdx.x;
    if (t < HH) {
        float p = 0.f, q = 0.f;
        #pragma unroll 8
        for (int i = 0; i < HH; i++) {
            p += Wg[t * HH + i] * a[i];
            q += Wm[t * HH + i] * a[HH + i];
        }
        sp[t] = p; sq[t] = q;
        ((float*)d_p4)[t] = p;
        ((float*)d_q4)[t] = q;
    }
    __syncthreads();
    if (t < AD) {
        float s = 0.f;
        for (int i = 0; i < HH; i++) s += Wd[t * HH + i] * sq[i];
        d_qd[t] = s;
    } else if (t == AD) {
        float s = 0.f;
        for (int i = 0; i < HH; i++) s += bd[i] * sq[i];
        d_c = s;
    } else if (t >= 32 && t < 32 + FD) {
        int r = t - 32;
        float s = 0.f;
        for (int j = 0; j < HH; j++) s += We[r * HH + j] * sp[j];
        d_wep[r] = s;
    } else if (t == 32 + FD) {
        float s = 0.f;
        for (int j = 0; j < HH; j++) s += be[j] * sp[j];
        d_c0 = s;
    }
    for (int idx = t; idx < AD * HH; idx += 256) {
        int r = idx >> 6, j = idx & 63;
        float s = 0.f;
        #pragma unroll 8
        for (int i = 0; i < HH; i++) s += Wd[r * HH + i] * Wm[i * HH + j];
        ((float*)d_M14)[idx] = s;
    }
    if (t < HH) {
        float s = 0.f;
        for (int i = 0; i < HH; i++) s += bd[i] * Wm[i * HH + t];
        ((float*)d_bm4)[t] = s;
    }
}

// ---------------- fused embed (+gp0) and per-edge logit --------------------------
__global__ __launch_bounds__(256) void k_pre(const float* __restrict__ tf,
                                             const float* __restrict__ We,
                                             const float* __restrict__ be,
                                             const float* __restrict__ fdg,
                                             const float* __restrict__ rij) {
    int b = blockIdx.x;
    if (b < NB_EMB) {
        int t = threadIdx.x, w = t >> 5, l = t & 31, sub = l & 15, half = l >> 4;
        int row = b * 16 + w * 2 + half;
        if (row > NN) return;
        float4 acc = make_float4(0.f, 0.f, 0.f, 0.f);
        float g = 0.f;
        if (row > 0) {
            int n = row - 1;
            const float* r = tf + n * FD;
            acc = ((const float4*)be)[sub];
            g = d_c0;
            #pragma unroll
            for (int tt = 0; tt < FD; tt++) {
                float x = __ldg(r + tt);
                float4 ww = ((const float4*)We)[tt * 16 + sub];
                acc.x += x * ww.x; acc.y += x * ww.y; acc.z += x * ww.z; acc.w += x * ww.w;
                g += x * d_wep[tt];
            }
        }
        d_hp0v[row * 16 + sub] = acc;
        if (sub == 0) d_gp0[row] = g;
    } else {
        int e = (b - NB_EMB) * 256 + threadIdx.x;
        if (e >= EE) return;
        float s = d_c + rij[e] * d_qd[9];
        const float* x = fdg + (long)e * FD;
        #pragma unroll
        for (int r = 0; r < FD; r++) s += x[r] * d_qd[r];
        d_elog[e] = s;
    }
}

// ---------------- softmax helper (width 16) --------------------------------------
__device__ __forceinline__ float softmax16(float logit) {
    float mx = logit;
    #pragma unroll
    for (int m = 8; m; m >>= 1) mx = fmaxf(mx, __shfl_xor_sync(0xffffffffu, mx, m, 16));
    float ex = __expf(logit - mx);
    float sum = ex;
    #pragma unroll
    for (int m = 8; m; m >>= 1) sum += __shfl_xor_sync(0xffffffffu, sum, m, 16);
    return ex / sum;
}

// ---------------- fused alpha + gather, iteration 1 ------------------------------
__global__ __launch_bounds__(256) void k_gather1(const int* __restrict__ se,
                                                 const int* __restrict__ bs,
                                                 const float* __restrict__ fdg,
                                                 const float* __restrict__ rij) {
    __shared__ float4 sbc[8][2][17];
    int t = threadIdx.x, w = t >> 5, l = t & 31, sub = l & 15, half = l >> 4;
    int n = (blockIdx.x * 8 + w) * 2 + half;     // < NN exactly

    int idx = se[n * KK + sub];
    int e   = bs[n * KK + sub];
    float v = __ldg(&d_gp0[idx]) + __ldg(&d_elog[e]);
    v = (v > 0.f) ? v : 0.2f * v;
    float alpha = softmax16((idx == 0) ? NEGINF : v);

    sbc[w][half][sub] = make_float4(alpha, __int_as_float(idx), __int_as_float(e), 0.f);
    __syncwarp();

    float4 acc = make_float4(0.f, 0.f, 0.f, 0.f);
    float ax = 0.f;
    #pragma unroll
    for (int k = 0; k < KK; k++) {
        float4 b = sbc[w][half][k];
        int i  = __float_as_int(b.y);
        int ee = __float_as_int(b.z);
        float4 vv = d_hp0v[i * 16 + sub];
        acc.x += b.x * vv.x; acc.y += b.x * vv.y; acc.z += b.x * vv.z; acc.w += b.x * vv.w;
        if (sub < AD) {
            float x = (sub < FD) ? fdg[(long)ee * FD + sub] : rij[ee];
            ax += b.x * x;
        }
    }
    d_accAv[n * 16 + sub] = acc;
    d_accX16[n * 16 + sub] = ax;
}

#define ELU1(x) ((x) > 0.f ? (x) : expm1f(x))

// ---------------- mega GEMM (FFMA2): hp1 = ELU(accA@Wg + accX@M1 + bm);
//                  th1 = hp1@Wg; tm1 = hp1@Wm; gp1/gm1 scalars --------------------
// dyn smem: sW 16K + sM 2.5K + sacc_dup 33K + sax 4.3K = 55.75 KiB
__global__ __launch_bounds__(256, 4) void k_mega(const float* __restrict__ Wg,
                                                 const float* __restrict__ Wm) {
    extern __shared__ float4 dyn[];
    float4* sW  = dyn;                       // 1024 float4
    float4* sM  = dyn + 1024;                // 160 float4
    float*  sacc = (float*)(dyn + 1184);     // 64 * 132 floats (duplicated pairs)
    float*  sax  = sacc + 64 * 132;          // 64 * 17

    int t = threadIdx.x;
    int nb0 = blockIdx.x * 64;
    for (int i = t; i < HH * 16; i += 256) sW[i] = ((const float4*)Wg)[i];
    for (int i = t; i < AD * 16; i += 256) sM[i] = d_M14[i];
    for (int i = t; i < 1024; i += 256) {
        int node = i >> 4, s = i & 15, n = nb0 + node;
        float4 v = (n < NN) ? d_accAv[n * 16 + s] : make_float4(0.f, 0.f, 0.f, 0.f);
        *(float4*)&sacc[node * 132 + s * 8]     = make_float4(v.x, v.x, v.y, v.y);
        *(float4*)&sacc[node * 132 + s * 8 + 4] = make_float4(v.z, v.z, v.w, v.w);
    }
    for (int i = t; i < 1024; i += 256) {
        int node = i >> 4, r = i & 15, n = nb0 + node;
        sax[node * 17 + r] = (n < NN) ? d_accX16[n * 16 + r] : 0.f;
    }
    __syncthreads();

    int ch = t & 15, g = t >> 4;
    int nl = g * 4;

    // ---- pass 1: hp1 = ELU(accA@Wg + accX@M1 + bm) ----
    ulonglong2 bmu = ((const ulonglong2*)d_bm4)[ch];
    u64 oA[4], oB[4];
    #pragma unroll
    for (int m = 0; m < 4; m++) { oA[m] = bmu.x; oB[m] = bmu.y; }
    #pragma unroll
    for (int s4 = 0; s4 < 16; s4++) {
        ulonglong2 w0 = ((ulonglong2*)sW)[(4 * s4 + 0) * 16 + ch];
        ulonglong2 w1 = ((ulonglong2*)sW)[(4 * s4 + 1) * 16 + ch];
        ulonglong2 w2 = ((ulonglong2*)sW)[(4 * s4 + 2) * 16 + ch];
        ulonglong2 w3 = ((ulonglong2*)sW)[(4 * s4 + 3) * 16 + ch];
        #pragma unroll
        for (int m = 0; m < 4; m++) {
            ulonglong2 a01 = *(ulonglong2*)&sacc[(nl + m) * 132 + s4 * 8];
            ulonglong2 a23 = *(ulonglong2*)&sacc[(nl + m) * 132 + s4 * 8 + 4];
            ffma2(oA[m], a01.x, w0.x); ffma2(oB[m], a01.x, w0.y);
            ffma2(oA[m], a01.y, w1.x); ffma2(oB[m], a01.y, w1.y);
            ffma2(oA[m], a23.x, w2.x); ffma2(oB[m], a23.x, w2.y);
            ffma2(oA[m], a23.y, w3.x); ffma2(oB[m], a23.y, w3.y);
        }
    }
    #pragma unroll
    for (int rr = 0; rr < AD; rr++) {
        ulonglong2 m4 = ((ulonglong2*)sM)[rr * 16 + ch];
        #pragma unroll
        for (int m = 0; m < 4; m++) {
            u64 xx = pack2(sax[(nl + m) * 17 + rr]);
            ffma2(oA[m], xx, m4.x); ffma2(oB[m], xx, m4.y);
        }
    }
    // ELU + scalar projections
    float h[4][4];
    #pragma unroll
    for (int m = 0; m < 4; m++) {
        float2 fa = unpack2(oA[m]), fb = unpack2(oB[m]);
        h[m][0] = ELU1(fa.x); h[m][1] = ELU1(fa.y);
        h[m][2] = ELU1(fb.x); h[m][3] = ELU1(fb.y);
    }
    {
        float4 p = d_p4[ch], q = d_q4[ch];
        float pp[4], qq[4];
        #pragma unroll
        for (int m = 0; m < 4; m++) {
            pp[m] = h[m][0]*p.x + h[m][1]*p.y + h[m][2]*p.z + h[m][3]*p.w;
            qq[m] = h[m][0]*q.x + h[m][1]*q.y + h[m][2]*q.z + h[m][3]*q.w;
        }
        #pragma unroll
        for (int mm = 8; mm; mm >>= 1) {
            #pragma unroll
            for (int m = 0; m < 4; m++) {
                pp[m] += __shfl_xor_sync(0xffffffffu, pp[m], mm, 16);
                qq[m] += __shfl_xor_sync(0xffffffffu, qq[m], mm, 16);
            }
        }
        if (ch == 0) {
            #pragma unroll
            for (int m = 0; m < 4; m++) {
                if (nb0 + nl + m < NN) {
                    d_gp1[nb0 + nl + m + 1] = pp[m];
                    d_gm1[nb0 + nl + m + 1] = qq[m];
                }
            }
        }
    }

    // overwrite sacc with hp1 (duplicated pairs)
    __syncthreads();
    #pragma unroll
    for (int m = 0; m < 4; m++) {
        *(float4*)&sacc[(nl + m) * 132 + ch * 8]     = make_float4(h[m][0], h[m][0], h[m][1], h[m][1]);
        *(float4*)&sacc[(nl + m) * 132 + ch * 8 + 4] = make_float4(h[m][2], h[m][2], h[m][3], h[m][3]);
    }
    __syncthreads();

    // ---- pass 2: th1 = hp1 @ Wg (sW still holds Wg) ----
    #pragma unroll
    for (int m = 0; m < 4; m++) { oA[m] = 0ull; oB[m] = 0ull; }
    #pragma unroll
    for (int s4 = 0; s4 < 16; s4++) {
        ulonglong2 w0 = ((ulonglong2*)sW)[(4 * s4 + 0) * 16 + ch];
        ulonglong2 w1 = ((ulonglong2*)sW)[(4 * s4 + 1) * 16 + ch];
        ulonglong2 w2 = ((ulonglong2*)sW)[(4 * s4 + 2) * 16 + ch];
        ulonglong2 w3 = ((ulonglong2*)sW)[(4 * s4 + 3) * 16 + ch];
        #pragma unroll
        for (int m = 0; m < 4; m++) {
            ulonglong2 a01 = *(ulonglong2*)&sacc[(nl + m) * 132 + s4 * 8];
            ulonglong2 a23 = *(ulonglong2*)&sacc[(nl + m) * 132 + s4 * 8 + 4];
            ffma2(oA[m], a01.x, w0.x); ffma2(oB[m], a01.x, w0.y);
            ffma2(oA[m], a01.y, w1.x); ffma2(oB[m], a01.y, w1.y);
            ffma2(oA[m], a23.x, w2.x); ffma2(oB[m], a23.x, w2.y);
            ffma2(oA[m], a23.y, w3.x); ffma2(oB[m], a23.y, w3.y);
        }
    }
    #pragma unroll
    for (int m = 0; m < 4; m++) {
        if (nb0 + nl + m < NN) {
            float2 fa = unpack2(oA[m]), fb = unpack2(oB[m]);
            d_th1v[(nb0 + nl + m + 1) * 16 + ch] = make_float4(fa.x, fa.y, fb.x, fb.y);
        }
    }
    __syncthreads();

    // ---- pass 3: tm1 = hp1 @ Wm ----
    for (int i = t; i < HH * 16; i += 256) sW[i] = ((const float4*)Wm)[i];
    __syncthreads();
    #pragma unroll
    for (int m = 0; m < 4; m++) { oA[m] = 0ull; oB[m] = 0ull; }
    #pragma unroll
    for (int s4 = 0; s4 < 16; s4++) {
        ulonglong2 w0 = ((ulonglong2*)sW)[(4 * s4 + 0) * 16 + ch];
        ulonglong2 w1 = ((ulonglong2*)sW)[(4 * s4 + 1) * 16 + ch];
        ulonglong2 w2 = ((ulonglong2*)sW)[(4 * s4 + 2) * 16 + ch];
        ulonglong2 w3 = ((ulonglong2*)sW)[(4 * s4 + 3) * 16 + ch];
        #pragma unroll
        for (int m = 0; m < 4; m++) {
            ulonglong2 a01 = *(ulonglong2*)&sacc[(nl + m) * 132 + s4 * 8];
            ulonglong2 a23 = *(ulonglong2*)&sacc[(nl + m) * 132 + s4 * 8 + 4];
            ffma2(oA[m], a01.x, w0.x); ffma2(oB[m], a01.x, w0.y);
            ffma2(oA[m], a01.y, w1.x); ffma2(oB[m], a01.y, w1.y);
            ffma2(oA[m], a23.x, w2.x); ffma2(oB[m], a23.x, w2.y);
            ffma2(oA[m], a23.y, w3.x); ffma2(oB[m], a23.y, w3.y);
        }
    }
    #pragma unroll
    for (int m = 0; m < 4; m++) {
        if (nb0 + nl + m < NN) {
            float2 fa = unpack2(oA[m]), fb = unpack2(oB[m]);
            d_tm1v[(nb0 + nl + m + 1) * 16 + ch] = make_float4(fa.x, fa.y, fb.x, fb.y);
        }
    }

    if (blockIdx.x == 0 && t < 16) {
        d_th1v[t] = make_float4(0.f, 0.f, 0.f, 0.f);
        d_tm1v[t] = make_float4(0.f, 0.f, 0.f, 0.f);
    }
    if (blockIdx.x == 0 && t == 0) { d_gp1[0] = 0.f; d_gm1[0] = 0.f; }
}

#define ELU4(o) \
    o.x = (o.x > 0.f) ? o.x : expm1f(o.x); \
    o.y = (o.y > 0.f) ? o.y : expm1f(o.y); \
    o.z = (o.z > 0.f) ? o.z : expm1f(o.z); \
    o.w = (o.w > 0.f) ? o.w : expm1f(o.w);

// ---------------- fused alpha + gather + ELU, iteration 2 (final) ----------------
__global__ __launch_bounds__(256) void k_gather2(const int* __restrict__ se,
                                                 const int* __restrict__ bs,
                                                 const int* __restrict__ su,
                                                 const int* __restrict__ sul) {
    __shared__ float4 sbc[8][2][17];
    int t = threadIdx.x, w = t >> 5, l = t & 31, sub = l & 15, half = l >> 4;
    int n = (blockIdx.x * 8 + w) * 2 + half;

    int idx = se[n * KK + sub];
    int e   = bs[n * KK + sub];
    int j   = __ldg(&su[e]);
    float msk = (__ldg(&sul[e]) > 0) ? 1.f : 0.f;
    float v = __ldg(&d_gp1[idx]) + msk * __ldg(&d_gm1[j]);
    v = (v > 0.f) ? v : 0.2f * v;
    float alpha = softmax16((idx == 0) ? NEGINF : v);

    sbc[w][half][sub] = make_float4(alpha, __int_as_float(idx), __int_as_float(j),
                                    alpha * msk);
    __syncwarp();

    float4 acc = make_float4(0.f, 0.f, 0.f, 0.f);
    #pragma unroll
    for (int k = 0; k < KK; k++) {
        float4 b = sbc[w][half][k];
        int i  = __float_as_int(b.y);
        int jj = __float_as_int(b.z);
        float4 vv = d_th1v[i * 16 + sub];
        acc.x += b.x * vv.x; acc.y += b.x * vv.y; acc.z += b.x * vv.z; acc.w += b.x * vv.w;
        float4 u = d_tm1v[jj * 16 + sub];
        acc.x += b.w * u.x; acc.y += b.w * u.y; acc.z += b.w * u.z; acc.w += b.w * u.w;
    }
    ELU4(acc)
    d_hp2v[(n + 1) * 16 + sub] = acc;
    if (blockIdx.x == 0 && t < 16) d_hp2v[t] = make_float4(0.f, 0.f, 0.f, 0.f);
}

// ---------------- readout ----------------------------------------------------------
__global__ __launch_bounds__(256) void k_out(const int* __restrict__ ls,
                                             float* __restrict__ out) {
    int wid = (blockIdx.x * blockDim.x + threadIdx.x) >> 5;
    int l = threadIdx.x & 31;
    int sub = l & 15;
    int mol = wid * 2 + (l >> 4);
    if (mol >= BBATCH) return;
    const int* row = ls + mol * MAXM;
    float4 acc = make_float4(0.f, 0.f, 0.f, 0.f);
    #pragma unroll 8
    for (int m = 0; m < MAXM; m++) {
        int i = __ldg(row + m);
        float4 v = d_hp2v[i * 16 + sub];
        acc.x += v.x; acc.y += v.y; acc.z += v.z; acc.w += v.w;
    }
    ((float4*)out)[mol * 16 + sub] = acc;
}

// ---------------- launch -----------------------------------------------------------
extern "C" void kernel_launch(void* const* d_in, const int* in_sizes, int n_in,
                              void* d_out, int out_size) {
    const float* tf  = (const float*)d_in[0];
    const float* fdg = (const float*)d_in[1];
    const float* rij = (const float*)d_in[2];
    const int*   se  = (const int*)d_in[3];
    const int*   bs  = (const int*)d_in[4];
    const int*   ls  = (const int*)d_in[5];
    const int*   su  = (const int*)d_in[6];
    const int*   sul = (const int*)d_in[7];
    const float* We  = (const float*)d_in[8];
    const float* be  = (const float*)d_in[9];
    const float* Wd  = (const float*)d_in[10];
    const float* bd  = (const float*)d_in[11];
    const float* Wg  = (const float*)d_in[12];
    const float* Wm  = (const float*)d_in[13];
    const float* ag  = (const float*)d_in[14];

    // sW 16384 + sM 2560 + sacc_dup 33792 + sax 4352 = 57088 B
    int mega_smem = 1184 * 16 + 64 * 132 * 4 + 64 * 17 * 4;
    static int smem_set = 0;
    if (!smem_set) {
        cudaFuncSetAttribute(k_mega, cudaFuncAttributeMaxDynamicSharedMemorySize, mega_smem);
        smem_set = 1;
    }

    int gat_blocks = NN / 16;               // 3125
    int gemm_blocks = (NN + 63) / 64;       // 782

    k_consts<<<1, 256>>>(Wg, Wm, ag, Wd, bd, We, be);
    k_pre<<<NB_EMB + NB_ELOG, 256>>>(tf, We, be, fdg, rij);

    k_gather1<<<gat_blocks, 256>>>(se, bs, fdg, rij);
    k_mega<<<gemm_blocks, 256, mega_smem>>>(Wg, Wm);
    k_gather2<<<gat_blocks, 256>>>(se, bs, su, sul);

    k_out<<<(BBATCH / 2 + 7) / 8, 256>>>(ls, (float*)d_out);
}

// round 9
// speedup vs baseline: 1.0877x; 1.0877x over previous
#include <cuda_runtime.h>
#include <math.h>

#define NN 50000
#define KK 16
#define EE 800000
#define BBATCH 1024
#define MAXM 48
#define FD 9
#define AD 10
#define HH 64
#define NEGINF (-1e9f)
#define NB_EMB 3126              // ceil((NN+1)/16)
#define NB_ELOG 3125             // EE/256

// ---------------- scratch ------------------------------------------------------
__device__ float4 d_hp0v[(NN + 1) * 16];
__device__ float4 d_th1v[(NN + 1) * 16];   // hp1 @ Wg (row 0 = 0)
__device__ float4 d_tm1v[(NN + 1) * 16];   // hp1 @ Wm (row 0 = 0)
__device__ float4 d_hp2v[(NN + 1) * 16];
__device__ float d_gp0[NN + 1];
__device__ float d_gp1[NN + 1];
__device__ float d_gm1[NN + 1];
__device__ float d_elog[EE];
__device__ float4 d_accAv[NN * 16];
__device__ float d_accX16[NN * 16];
__device__ float4 d_p4[16];
__device__ float4 d_q4[16];
__device__ float d_qd[AD];
__device__ float d_c;
__device__ float d_wep[FD];      // We @ p
__device__ float d_c0;           // be . p
__device__ float4 d_M14[AD * 16];
__device__ float4 d_bm4[16];

// ---------------- constants -----------------------------------------------------
__global__ __launch_bounds__(256) void k_consts(const float* __restrict__ Wg,
                                                const float* __restrict__ Wm,
                                                const float* __restrict__ a,
                                                const float* __restrict__ Wd,
                                                const float* __restrict__ bd,
                                                const float* __restrict__ We,
                                                const float* __restrict__ be) {
    __shared__ float sp[HH], sq[HH];
    int t = threadIdx.x;
    if (t < HH) {
        float p = 0.f, q = 0.f;
        #pragma unroll 8
        for (int i = 0; i < HH; i++) {
            p += Wg[t * HH + i] * a[i];
            q += Wm[t * HH + i] * a[HH + i];
        }
        sp[t] = p; sq[t] = q;
        ((float*)d_p4)[t] = p;
        ((float*)d_q4)[t] = q;
    }
    __syncthreads();
    if (t < AD) {
        float s = 0.f;
        for (int i = 0; i < HH; i++) s += Wd[t * HH + i] * sq[i];
        d_qd[t] = s;
    } else if (t == AD) {
        float s = 0.f;
        for (int i = 0; i < HH; i++) s += bd[i] * sq[i];
        d_c = s;
    } else if (t >= 32 && t < 32 + FD) {
        int r = t - 32;
        float s = 0.f;
        for (int j = 0; j < HH; j++) s += We[r * HH + j] * sp[j];
        d_wep[r] = s;
    } else if (t == 32 + FD) {
        float s = 0.f;
        for (int j = 0; j < HH; j++) s += be[j] * sp[j];
        d_c0 = s;
    }
    for (int idx = t; idx < AD * HH; idx += 256) {
        int r = idx >> 6, j = idx & 63;
        float s = 0.f;
        #pragma unroll 8
        for (int i = 0; i < HH; i++) s += Wd[r * HH + i] * Wm[i * HH + j];
        ((float*)d_M14)[idx] = s;
    }
    if (t < HH) {
        float s = 0.f;
        for (int i = 0; i < HH; i++) s += bd[i] * Wm[i * HH + t];
        ((float*)d_bm4)[t] = s;
    }
}

// ---------------- fused embed (+gp0) and per-edge logit --------------------------
__global__ __launch_bounds__(256) void k_pre(const float* __restrict__ tf,
                                             const float* __restrict__ We,
                                             const float* __restrict__ be,
                                             const float* __restrict__ fdg,
                                             const float* __restrict__ rij) {
    int b = blockIdx.x;
    if (b < NB_EMB) {
        int t = threadIdx.x, w = t >> 5, l = t & 31, sub = l & 15, half = l >> 4;
        int row = b * 16 + w * 2 + half;
        if (row > NN) return;
        float4 acc = make_float4(0.f, 0.f, 0.f, 0.f);
        float g = 0.f;
        if (row > 0) {
            int n = row - 1;
            const float* r = tf + n * FD;
            acc = ((const float4*)be)[sub];
            g = d_c0;
            #pragma unroll
            for (int tt = 0; tt < FD; tt++) {
                float x = __ldg(r + tt);
                float4 ww = ((const float4*)We)[tt * 16 + sub];
                acc.x += x * ww.x; acc.y += x * ww.y; acc.z += x * ww.z; acc.w += x * ww.w;
                g += x * d_wep[tt];
            }
        }
        d_hp0v[row * 16 + sub] = acc;
        if (sub == 0) d_gp0[row] = g;
    } else {
        int e = (b - NB_EMB) * 256 + threadIdx.x;
        if (e >= EE) return;
        float s = d_c + rij[e] * d_qd[9];
        const float* x = fdg + (long)e * FD;
        #pragma unroll
        for (int r = 0; r < FD; r++) s += x[r] * d_qd[r];
        d_elog[e] = s;
    }
}

// ---------------- softmax helper (width 16) --------------------------------------
__device__ __forceinline__ float softmax16(float logit) {
    float mx = logit;
    #pragma unroll
    for (int m = 8; m; m >>= 1) mx = fmaxf(mx, __shfl_xor_sync(0xffffffffu, mx, m, 16));
    float ex = __expf(logit - mx);
    float sum = ex;
    #pragma unroll
    for (int m = 8; m; m >>= 1) sum += __shfl_xor_sync(0xffffffffu, sum, m, 16);
    return ex / sum;
}

// ---------------- fused alpha + gather, iteration 1 ------------------------------
__global__ __launch_bounds__(256) void k_gather1(const int* __restrict__ se,
                                                 const int* __restrict__ bs,
                                                 const float* __restrict__ fdg,
                                                 const float* __restrict__ rij) {
    __shared__ float4 sbc[8][2][17];
    int t = threadIdx.x, w = t >> 5, l = t & 31, sub = l & 15, half = l >> 4;
    int n = (blockIdx.x * 8 + w) * 2 + half;     // < NN exactly

    int idx = se[n * KK + sub];
    int e   = bs[n * KK + sub];
    float v = __ldg(&d_gp0[idx]) + __ldg(&d_elog[e]);
    v = (v > 0.f) ? v : 0.2f * v;
    float alpha = softmax16((idx == 0) ? NEGINF : v);

    sbc[w][half][sub] = make_float4(alpha, __int_as_float(idx), __int_as_float(e), 0.f);
    __syncwarp();

    float4 acc = make_float4(0.f, 0.f, 0.f, 0.f);
    float ax = 0.f;
    #pragma unroll
    for (int k = 0; k < KK; k++) {
        float4 b = sbc[w][half][k];
        int i  = __float_as_int(b.y);
        int ee = __float_as_int(b.z);
        float4 vv = d_hp0v[i * 16 + sub];
        acc.x += b.x * vv.x; acc.y += b.x * vv.y; acc.z += b.x * vv.z; acc.w += b.x * vv.w;
        if (sub < AD) {
            float x = (sub < FD) ? fdg[(long)ee * FD + sub] : rij[ee];
            ax += b.x * x;
        }
    }
    d_accAv[n * 16 + sub] = acc;
    d_accX16[n * 16 + sub] = ax;
}

#define FMA4(o, a, w0, w1, w2, w3)                                     \
    o.x += a.x * w0.x + a.y * w1.x + a.z * w2.x + a.w * w3.x;          \
    o.y += a.x * w0.y + a.y * w1.y + a.z * w2.y + a.w * w3.y;          \
    o.z += a.x * w0.z + a.y * w1.z + a.z * w2.z + a.w * w3.z;          \
    o.w += a.x * w0.w + a.y * w1.w + a.z * w2.w + a.w * w3.w;

#define ELU4(o) \
    o.x = (o.x > 0.f) ? o.x : expm1f(o.x); \
    o.y = (o.y > 0.f) ? o.y : expm1f(o.y); \
    o.z = (o.z > 0.f) ? o.z : expm1f(o.z); \
    o.w = (o.w > 0.f) ? o.w : expm1f(o.w);

// ---------------- mega GEMM: hp1 = ELU(accA@Wg + accX@M1 + bm);
//                  th1 = hp1@Wg; tm1 = hp1@Wm (fused); gp1/gm1 scalars ------------
// dyn smem: sWg 16K + sWm 16K + sacc 17K + sax 4.25K = 53.25 KiB  (4 blocks/SM)
__global__ __launch_bounds__(256, 3) void k_mega(const float* __restrict__ Wg,
                                                 const float* __restrict__ Wm) {
    extern __shared__ float4 dyn[];
    float4* sWg = dyn;                       // 1024 float4
    float4* sWm = dyn + 1024;                // 1024 float4
    float*  sacc = (float*)(dyn + 2048);     // 64*68 floats (accA, then hp1)
    float*  sax  = sacc + 64 * 68;           // 64*17 floats

    int t = threadIdx.x;
    int nb0 = blockIdx.x * 64;
    for (int i = t; i < HH * 16; i += 256) {
        sWg[i] = ((const float4*)Wg)[i];
        sWm[i] = ((const float4*)Wm)[i];
    }
    for (int i = t; i < 1024; i += 256) {
        int node = i >> 4, s = i & 15, n = nb0 + node;
        float4 v = (n < NN) ? d_accAv[n * 16 + s] : make_float4(0.f, 0.f, 0.f, 0.f);
        *(float4*)&sacc[node * 68 + s * 4] = v;
    }
    for (int i = t; i < 1024; i += 256) {
        int node = i >> 4, r = i & 15, n = nb0 + node;
        sax[node * 17 + r] = (n < NN) ? d_accX16[n * 16 + r] : 0.f;
    }
    __syncthreads();

    int ch = t & 15, g = t >> 4;
    int nl = g * 4;

    // ---- pass 1: hp1 = ELU(accA@Wg + accX@M1 + bm) ----
    float4 bm = __ldg(&d_bm4[ch]);
    float4 o0 = bm, o1 = bm, o2 = bm, o3 = bm;
    #pragma unroll
    for (int s4 = 0; s4 < 16; s4++) {
        float4 w0 = sWg[(4 * s4 + 0) * 16 + ch];
        float4 w1 = sWg[(4 * s4 + 1) * 16 + ch];
        float4 w2 = sWg[(4 * s4 + 2) * 16 + ch];
        float4 w3 = sWg[(4 * s4 + 3) * 16 + ch];
        float4 a0 = *(float4*)&sacc[(nl + 0) * 68 + s4 * 4];
        float4 a1 = *(float4*)&sacc[(nl + 1) * 68 + s4 * 4];
        float4 a2 = *(float4*)&sacc[(nl + 2) * 68 + s4 * 4];
        float4 a3 = *(float4*)&sacc[(nl + 3) * 68 + s4 * 4];
        FMA4(o0, a0, w0, w1, w2, w3)
        FMA4(o1, a1, w0, w1, w2, w3)
        FMA4(o2, a2, w0, w1, w2, w3)
        FMA4(o3, a3, w0, w1, w2, w3)
    }
    #pragma unroll
    for (int rr = 0; rr < AD; rr++) {
        float4 m = __ldg(&d_M14[rr * 16 + ch]);
        float x0 = sax[(nl + 0) * 17 + rr], x1 = sax[(nl + 1) * 17 + rr];
        float x2 = sax[(nl + 2) * 17 + rr], x3 = sax[(nl + 3) * 17 + rr];
        o0.x += x0 * m.x; o0.y += x0 * m.y; o0.z += x0 * m.z; o0.w += x0 * m.w;
        o1.x += x1 * m.x; o1.y += x1 * m.y; o1.z += x1 * m.z; o1.w += x1 * m.w;
        o2.x += x2 * m.x; o2.y += x2 * m.y; o2.z += x2 * m.z; o2.w += x2 * m.w;
        o3.x += x3 * m.x; o3.y += x3 * m.y; o3.z += x3 * m.z; o3.w += x3 * m.w;
    }
    ELU4(o0) ELU4(o1) ELU4(o2) ELU4(o3)

    // gp1/gm1 scalars
    {
        float4 p = __ldg(&d_p4[ch]), q = __ldg(&d_q4[ch]);
        float pp0 = o0.x*p.x + o0.y*p.y + o0.z*p.z + o0.w*p.w;
        float pp1 = o1.x*p.x + o1.y*p.y + o1.z*p.z + o1.w*p.w;
        float pp2 = o2.x*p.x + o2.y*p.y + o2.z*p.z + o2.w*p.w;
        float pp3 = o3.x*p.x + o3.y*p.y + o3.z*p.z + o3.w*p.w;
        float qq0 = o0.x*q.x + o0.y*q.y + o0.z*q.z + o0.w*q.w;
        float qq1 = o1.x*q.x + o1.y*q.y + o1.z*q.z + o1.w*q.w;
        float qq2 = o2.x*q.x + o2.y*q.y + o2.z*q.z + o2.w*q.w;
        float qq3 = o3.x*q.x + o3.y*q.y + o3.z*q.z + o3.w*q.w;
        #pragma unroll
        for (int m = 8; m; m >>= 1) {
            pp0 += __shfl_xor_sync(0xffffffffu, pp0, m, 16);
            pp1 += __shfl_xor_sync(0xffffffffu, pp1, m, 16);
            pp2 += __shfl_xor_sync(0xffffffffu, pp2, m, 16);
            pp3 += __shfl_xor_sync(0xffffffffu, pp3, m, 16);
            qq0 += __shfl_xor_sync(0xffffffffu, qq0, m, 16);
            qq1 += __shfl_xor_sync(0xffffffffu, qq1, m, 16);
            qq2 += __shfl_xor_sync(0xffffffffu, qq2, m, 16);
            qq3 += __shfl_xor_sync(0xffffffffu, qq3, m, 16);
        }
        if (ch == 0) {
            if (nb0 + nl + 0 < NN) { d_gp1[nb0 + nl + 1] = pp0; d_gm1[nb0 + nl + 1] = qq0; }
            if (nb0 + nl + 1 < NN) { d_gp1[nb0 + nl + 2] = pp1; d_gm1[nb0 + nl + 2] = qq1; }
            if (nb0 + nl + 2 < NN) { d_gp1[nb0 + nl + 3] = pp2; d_gm1[nb0 + nl + 3] = qq2; }
            if (nb0 + nl + 3 < NN) { d_gp1[nb0 + nl + 4] = pp3; d_gm1[nb0 + nl + 4] = qq3; }
        }
    }

    // Overwrite this g-group's own sacc rows with hp1. Rows 4g..4g+3 are read and
    // written ONLY by the 16 threads sharing g (one half-warp) → warp-level sync
    // suffices; no block barrier needed.
    __syncwarp();
    *(float4*)&sacc[(nl + 0) * 68 + ch * 4] = o0;
    *(float4*)&sacc[(nl + 1) * 68 + ch * 4] = o1;
    *(float4*)&sacc[(nl + 2) * 68 + ch * 4] = o2;
    *(float4*)&sacc[(nl + 3) * 68 + ch * 4] = o3;
    __syncwarp();

    // ---- fused passes 2+3: th1 = hp1@Wg, tm1 = hp1@Wm (one activation read) ----
    float4 uA0 = make_float4(0.f,0.f,0.f,0.f), uA1 = uA0, uA2 = uA0, uA3 = uA0;
    float4 uB0 = uA0, uB1 = uA0, uB2 = uA0, uB3 = uA0;
    #pragma unroll
    for (int s4 = 0; s4 < 16; s4++) {
        float4 a0 = *(float4*)&sacc[(nl + 0) * 68 + s4 * 4];
        float4 a1 = *(float4*)&sacc[(nl + 1) * 68 + s4 * 4];
        float4 a2 = *(float4*)&sacc[(nl + 2) * 68 + s4 * 4];
        float4 a3 = *(float4*)&sacc[(nl + 3) * 68 + s4 * 4];
        {
            float4 w0 = sWg[(4 * s4 + 0) * 16 + ch];
            float4 w1 = sWg[(4 * s4 + 1) * 16 + ch];
            float4 w2 = sWg[(4 * s4 + 2) * 16 + ch];
            float4 w3 = sWg[(4 * s4 + 3) * 16 + ch];
            FMA4(uA0, a0, w0, w1, w2, w3)
            FMA4(uA1, a1, w0, w1, w2, w3)
            FMA4(uA2, a2, w0, w1, w2, w3)
            FMA4(uA3, a3, w0, w1, w2, w3)
        }
        {
            float4 w0 = sWm[(4 * s4 + 0) * 16 + ch];
            float4 w1 = sWm[(4 * s4 + 1) * 16 + ch];
            float4 w2 = sWm[(4 * s4 + 2) * 16 + ch];
            float4 w3 = sWm[(4 * s4 + 3) * 16 + ch];
            FMA4(uB0, a0, w0, w1, w2, w3)
            FMA4(uB1, a1, w0, w1, w2, w3)
            FMA4(uB2, a2, w0, w1, w2, w3)
            FMA4(uB3, a3, w0, w1, w2, w3)
        }
    }
    if (nb0 + nl + 0 < NN) { d_th1v[(nb0 + nl + 1) * 16 + ch] = uA0; d_tm1v[(nb0 + nl + 1) * 16 + ch] = uB0; }
    if (nb0 + nl + 1 < NN) { d_th1v[(nb0 + nl + 2) * 16 + ch] = uA1; d_tm1v[(nb0 + nl + 2) * 16 + ch] = uB1; }
    if (nb0 + nl + 2 < NN) { d_th1v[(nb0 + nl + 3) * 16 + ch] = uA2; d_tm1v[(nb0 + nl + 3) * 16 + ch] = uB2; }
    if (nb0 + nl + 3 < NN) { d_th1v[(nb0 + nl + 4) * 16 + ch] = uA3; d_tm1v[(nb0 + nl + 4) * 16 + ch] = uB3; }

    if (blockIdx.x == 0 && t < 16) {
        d_th1v[t] = make_float4(0.f, 0.f, 0.f, 0.f);
        d_tm1v[t] = make_float4(0.f, 0.f, 0.f, 0.f);
    }
    if (blockIdx.x == 0 && t == 0) { d_gp1[0] = 0.f; d_gm1[0] = 0.f; }
}

// ---------------- fused alpha + gather + ELU, iteration 2 (final) ----------------
__global__ __launch_bounds__(256) void k_gather2(const int* __restrict__ se,
                                                 const int* __restrict__ bs,
                                                 const int* __restrict__ su,
                                                 const int* __restrict__ sul) {
    __shared__ float4 sbc[8][2][17];
    int t = threadIdx.x, w = t >> 5, l = t & 31, sub = l & 15, half = l >> 4;
    int n = (blockIdx.x * 8 + w) * 2 + half;

    int idx = se[n * KK + sub];
    int e   = bs[n * KK + sub];
    int j   = __ldg(&su[e]);
    float msk = (__ldg(&sul[e]) > 0) ? 1.f : 0.f;
    float v = __ldg(&d_gp1[idx]) + msk * __ldg(&d_gm1[j]);
    v = (v > 0.f) ? v : 0.2f * v;
    float alpha = softmax16((idx == 0) ? NEGINF : v);

    sbc[w][half][sub] = make_float4(alpha, __int_as_float(idx), __int_as_float(j),
                                    alpha * msk);
    __syncwarp();

    float4 acc = make_float4(0.f, 0.f, 0.f, 0.f);
    #pragma unroll
    for (int k = 0; k < KK; k++) {
        float4 b = sbc[w][half][k];
        int i  = __float_as_int(b.y);
        int jj = __float_as_int(b.z);
        float4 vv = d_th1v[i * 16 + sub];
        acc.x += b.x * vv.x; acc.y += b.x * vv.y; acc.z += b.x * vv.z; acc.w += b.x * vv.w;
        float4 u = d_tm1v[jj * 16 + sub];
        acc.x += b.w * u.x; acc.y += b.w * u.y; acc.z += b.w * u.z; acc.w += b.w * u.w;
    }
    ELU4(acc)
    d_hp2v[(n + 1) * 16 + sub] = acc;
    if (blockIdx.x == 0 && t < 16) d_hp2v[t] = make_float4(0.f, 0.f, 0.f, 0.f);
}

// ---------------- readout ----------------------------------------------------------
__global__ __launch_bounds__(256) void k_out(const int* __restrict__ ls,
                                             float* __restrict__ out) {
    int wid = (blockIdx.x * blockDim.x + threadIdx.x) >> 5;
    int l = threadIdx.x & 31;
    int sub = l & 15;
    int mol = wid * 2 + (l >> 4);
    if (mol >= BBATCH) return;
    const int* row = ls + mol * MAXM;
    float4 acc = make_float4(0.f, 0.f, 0.f, 0.f);
    #pragma unroll 8
    for (int m = 0; m < MAXM; m++) {
        int i = __ldg(row + m);
        float4 v = d_hp2v[i * 16 + sub];
        acc.x += v.x; acc.y += v.y; acc.z += v.z; acc.w += v.w;
    }
    ((float4*)out)[mol * 16 + sub] = acc;
}

// ---------------- launch -----------------------------------------------------------
extern "C" void kernel_launch(void* const* d_in, const int* in_sizes, int n_in,
                              void* d_out, int out_size) {
    const float* tf  = (const float*)d_in[0];
    const float* fdg = (const float*)d_in[1];
    const float* rij = (const float*)d_in[2];
    const int*   se  = (const int*)d_in[3];
    const int*   bs  = (const int*)d_in[4];
    const int*   ls  = (const int*)d_in[5];
    const int*   su  = (const int*)d_in[6];
    const int*   sul = (const int*)d_in[7];
    const float* We  = (const float*)d_in[8];
    const float* be  = (const float*)d_in[9];
    const float* Wd  = (const float*)d_in[10];
    const float* bd  = (const float*)d_in[11];
    const float* Wg  = (const float*)d_in[12];
    const float* Wm  = (const float*)d_in[13];
    const float* ag  = (const float*)d_in[14];

    // sWg 16384 + sWm 16384 + sacc 17408 + sax 4352 = 54528 B
    int mega_smem = 2048 * 16 + 64 * 68 * 4 + 64 * 17 * 4;
    static int smem_set = 0;
    if (!smem_set) {
        cudaFuncSetAttribute(k_mega, cudaFuncAttributeMaxDynamicSharedMemorySize, mega_smem);
        smem_set = 1;
    }

    int gat_blocks = NN / 16;               // 3125
    int gemm_blocks = (NN + 63) / 64;       // 782

    k_consts<<<1, 256>>>(Wg, Wm, ag, Wd, bd, We, be);
    k_pre<<<NB_EMB + NB_ELOG, 256>>>(tf, We, be, fdg, rij);

    k_gather1<<<gat_blocks, 256>>>(se, bs, fdg, rij);
    k_mega<<<gemm_blocks, 256, mega_smem>>>(Wg, Wm);
    k_gather2<<<gat_blocks, 256>>>(se, bs, su, sul);

    k_out<<<(BBATCH / 2 + 7) / 8, 256>>>(ls, (float*)d_out);
}

// round 10
// speedup vs baseline: 1.2310x; 1.1318x over previous
#include <cuda_runtime.h>
#include <cuda_fp16.h>
#include <math.h>

#define NN 50000
#define KK 16
#define EE 800000
#define BBATCH 1024
#define MAXM 48
#define FD 9
#define AD 10
#define HH 64
#define NEGINF (-1e9f)
#define NB_EMB 3126              // ceil((NN+1)/16)
#define NB_ELOG 3125             // EE/256

__device__ __forceinline__ unsigned pack_half2(float a, float b) {
    __half2 h = __floats2half2_rn(a, b);
    return *reinterpret_cast<unsigned*>(&h);
}
__device__ __forceinline__ float2 unpack_half2(unsigned u) {
    __half2 h = *reinterpret_cast<__half2*>(&u);
    return __half22float2(h);
}

// ---------------- scratch ------------------------------------------------------
__device__ uint2  d_hp0h[(NN + 1) * 16];   // fp16 node embeddings (row 0 = 0)
__device__ uint2  d_th1h[(NN + 1) * 16];   // fp16 hp1 @ Wg
__device__ uint2  d_tm1h[(NN + 1) * 16];   // fp16 hp1 @ Wm
__device__ float4 d_hp2v[(NN + 1) * 16];
__device__ float d_gp0[NN + 1];
__device__ float d_gp1[NN + 1];
__device__ float d_gm1[NN + 1];
__device__ float d_elog[EE];
__device__ float4 d_accAv[NN * 16];
__device__ float d_accX16[NN * 16];
__device__ float4 d_p4[16];
__device__ float4 d_q4[16];
__device__ float d_qd[AD];
__device__ float d_c;
__device__ float d_wep[FD];      // We @ p
__device__ float d_c0;           // be . p
__device__ float4 d_M14[AD * 16];
__device__ float4 d_bm4[16];

// ---------------- constants (5 blocks: 0 = vectors, 1-4 = M14 slices) ------------
__global__ __launch_bounds__(256) void k_consts(const float* __restrict__ Wg,
                                                const float* __restrict__ Wm,
                                                const float* __restrict__ a,
                                                const float* __restrict__ Wd,
                                                const float* __restrict__ bd,
                                                const float* __restrict__ We,
                                                const float* __restrict__ be) {
    int t = threadIdx.x;
    if (blockIdx.x == 0) {
        __shared__ float sp[HH], sq[HH];
        if (t < HH) {
            float p = 0.f, q = 0.f;
            #pragma unroll 8
            for (int i = 0; i < HH; i++) {
                p += Wg[t * HH + i] * a[i];
                q += Wm[t * HH + i] * a[HH + i];
            }
            sp[t] = p; sq[t] = q;
            ((float*)d_p4)[t] = p;
            ((float*)d_q4)[t] = q;
        }
        __syncthreads();
        if (t < AD) {
            float s = 0.f;
            for (int i = 0; i < HH; i++) s += Wd[t * HH + i] * sq[i];
            d_qd[t] = s;
        } else if (t == AD) {
            float s = 0.f;
            for (int i = 0; i < HH; i++) s += bd[i] * sq[i];
            d_c = s;
        } else if (t >= 32 && t < 32 + FD) {
            int r = t - 32;
            float s = 0.f;
            for (int j = 0; j < HH; j++) s += We[r * HH + j] * sp[j];
            d_wep[r] = s;
        } else if (t == 32 + FD) {
            float s = 0.f;
            for (int j = 0; j < HH; j++) s += be[j] * sp[j];
            d_c0 = s;
        }
        if (t < HH) {
            float s = 0.f;
            for (int i = 0; i < HH; i++) s += bd[i] * Wm[i * HH + t];
            ((float*)d_bm4)[t] = s;
        }
    } else {
        // M14[r][j] = Wd row r . Wm col j; 640 entries over 4 blocks
        int idx = (blockIdx.x - 1) * 160 + t;
        if (t < 160 && idx < AD * HH) {
            int r = idx >> 6, j = idx & 63;
            float s = 0.f;
            #pragma unroll 8
            for (int i = 0; i < HH; i++) s += Wd[r * HH + i] * Wm[i * HH + j];
            ((float*)d_M14)[idx] = s;
        }
    }
}

// ---------------- fused embed (+gp0, fp16 hp0) and per-edge logit ----------------
__global__ __launch_bounds__(256) void k_pre(const float* __restrict__ tf,
                                             const float* __restrict__ We,
                                             const float* __restrict__ be,
                                             const float* __restrict__ fdg,
                                             const float* __restrict__ rij) {
    int b = blockIdx.x;
    if (b < NB_EMB) {
        int t = threadIdx.x, w = t >> 5, l = t & 31, sub = l & 15, half = l >> 4;
        int row = b * 16 + w * 2 + half;
        if (row > NN) return;
        float4 acc = make_float4(0.f, 0.f, 0.f, 0.f);
        float g = 0.f;
        if (row > 0) {
            int n = row - 1;
            const float* r = tf + n * FD;
            acc = ((const float4*)be)[sub];
            g = d_c0;
            #pragma unroll
            for (int tt = 0; tt < FD; tt++) {
                float x = __ldg(r + tt);
                float4 ww = ((const float4*)We)[tt * 16 + sub];
                acc.x += x * ww.x; acc.y += x * ww.y; acc.z += x * ww.z; acc.w += x * ww.w;
                g += x * d_wep[tt];
            }
        }
        uint2 pk;
        pk.x = pack_half2(acc.x, acc.y);
        pk.y = pack_half2(acc.z, acc.w);
        d_hp0h[row * 16 + sub] = pk;
        if (sub == 0) d_gp0[row] = g;
    } else {
        int e = (b - NB_EMB) * 256 + threadIdx.x;
        if (e >= EE) return;
        float s = d_c + rij[e] * d_qd[9];
        const float* x = fdg + (long)e * FD;
        #pragma unroll
        for (int r = 0; r < FD; r++) s += x[r] * d_qd[r];
        d_elog[e] = s;
    }
}

// ---------------- softmax helper (width 16) --------------------------------------
__device__ __forceinline__ float softmax16(float logit) {
    float mx = logit;
    #pragma unroll
    for (int m = 8; m; m >>= 1) mx = fmaxf(mx, __shfl_xor_sync(0xffffffffu, mx, m, 16));
    float ex = __expf(logit - mx);
    float sum = ex;
    #pragma unroll
    for (int m = 8; m; m >>= 1) sum += __shfl_xor_sync(0xffffffffu, sum, m, 16);
    return ex / sum;
}

// ---------------- fused alpha + gather, iteration 1 (fp16 hp0 table) -------------
__global__ __launch_bounds__(256) void k_gather1(const int* __restrict__ se,
                                                 const int* __restrict__ bs,
                                                 const float* __restrict__ fdg,
                                                 const float* __restrict__ rij) {
    __shared__ float4 sbc[8][2][17];
    int t = threadIdx.x, w = t >> 5, l = t & 31, sub = l & 15, half = l >> 4;
    int n = (blockIdx.x * 8 + w) * 2 + half;     // < NN exactly

    int idx = se[n * KK + sub];
    int e   = bs[n * KK + sub];
    float v = __ldg(&d_gp0[idx]) + __ldg(&d_elog[e]);
    v = (v > 0.f) ? v : 0.2f * v;
    float alpha = softmax16((idx == 0) ? NEGINF : v);

    sbc[w][half][sub] = make_float4(alpha, __int_as_float(idx), __int_as_float(e), 0.f);
    __syncwarp();

    float4 acc = make_float4(0.f, 0.f, 0.f, 0.f);
    float ax = 0.f;
    #pragma unroll
    for (int k = 0; k < KK; k++) {
        float4 b = sbc[w][half][k];
        int i  = __float_as_int(b.y);
        int ee = __float_as_int(b.z);
        uint2 hv = d_hp0h[i * 16 + sub];
        float2 vA = unpack_half2(hv.x), vB = unpack_half2(hv.y);
        acc.x += b.x * vA.x; acc.y += b.x * vA.y;
        acc.z += b.x * vB.x; acc.w += b.x * vB.y;
        if (sub < AD) {
            float x = (sub < FD) ? fdg[(long)ee * FD + sub] : rij[ee];
            ax += b.x * x;
        }
    }
    d_accAv[n * 16 + sub] = acc;
    d_accX16[n * 16 + sub] = ax;
}

#define FMA4(o, a, w0, w1, w2, w3)                                     \
    o.x += a.x * w0.x + a.y * w1.x + a.z * w2.x + a.w * w3.x;          \
    o.y += a.x * w0.y + a.y * w1.y + a.z * w2.y + a.w * w3.y;          \
    o.z += a.x * w0.z + a.y * w1.z + a.z * w2.z + a.w * w3.z;          \
    o.w += a.x * w0.w + a.y * w1.w + a.z * w2.w + a.w * w3.w;

#define ELU4(o) \
    o.x = (o.x > 0.f) ? o.x : expm1f(o.x); \
    o.y = (o.y > 0.f) ? o.y : expm1f(o.y); \
    o.z = (o.z > 0.f) ? o.z : expm1f(o.z); \
    o.w = (o.w > 0.f) ? o.w : expm1f(o.w);

// ---------------- mega GEMM: hp1 = ELU(accA@Wg + accX@M1 + bm);
//                  th1 = hp1@Wg; tm1 = hp1@Wm (fused, fp16 out); gp1/gm1 ---------
__global__ __launch_bounds__(256, 3) void k_mega(const float* __restrict__ Wg,
                                                 const float* __restrict__ Wm) {
    extern __shared__ float4 dyn[];
    float4* sWg = dyn;                       // 1024 float4
    float4* sWm = dyn + 1024;                // 1024 float4
    float*  sacc = (float*)(dyn + 2048);     // 64*68 floats (accA, then hp1)
    float*  sax  = sacc + 64 * 68;           // 64*17 floats

    int t = threadIdx.x;
    int nb0 = blockIdx.x * 64;
    for (int i = t; i < HH * 16; i += 256) {
        sWg[i] = ((const float4*)Wg)[i];
        sWm[i] = ((const float4*)Wm)[i];
    }
    for (int i = t; i < 1024; i += 256) {
        int node = i >> 4, s = i & 15, n = nb0 + node;
        float4 v = (n < NN) ? d_accAv[n * 16 + s] : make_float4(0.f, 0.f, 0.f, 0.f);
        *(float4*)&sacc[node * 68 + s * 4] = v;
    }
    for (int i = t; i < 1024; i += 256) {
        int node = i >> 4, r = i & 15, n = nb0 + node;
        sax[node * 17 + r] = (n < NN) ? d_accX16[n * 16 + r] : 0.f;
    }
    __syncthreads();

    int ch = t & 15, g = t >> 4;
    int nl = g * 4;

    // ---- pass 1: hp1 = ELU(accA@Wg + accX@M1 + bm) ----
    float4 bm = __ldg(&d_bm4[ch]);
    float4 o0 = bm, o1 = bm, o2 = bm, o3 = bm;
    #pragma unroll
    for (int s4 = 0; s4 < 16; s4++) {
        float4 w0 = sWg[(4 * s4 + 0) * 16 + ch];
        float4 w1 = sWg[(4 * s4 + 1) * 16 + ch];
        float4 w2 = sWg[(4 * s4 + 2) * 16 + ch];
        float4 w3 = sWg[(4 * s4 + 3) * 16 + ch];
        float4 a0 = *(float4*)&sacc[(nl + 0) * 68 + s4 * 4];
        float4 a1 = *(float4*)&sacc[(nl + 1) * 68 + s4 * 4];
        float4 a2 = *(float4*)&sacc[(nl + 2) * 68 + s4 * 4];
        float4 a3 = *(float4*)&sacc[(nl + 3) * 68 + s4 * 4];
        FMA4(o0, a0, w0, w1, w2, w3)
        FMA4(o1, a1, w0, w1, w2, w3)
        FMA4(o2, a2, w0, w1, w2, w3)
        FMA4(o3, a3, w0, w1, w2, w3)
    }
    #pragma unroll
    for (int rr = 0; rr < AD; rr++) {
        float4 m = __ldg(&d_M14[rr * 16 + ch]);
        float x0 = sax[(nl + 0) * 17 + rr], x1 = sax[(nl + 1) * 17 + rr];
        float x2 = sax[(nl + 2) * 17 + rr], x3 = sax[(nl + 3) * 17 + rr];
        o0.x += x0 * m.x; o0.y += x0 * m.y; o0.z += x0 * m.z; o0.w += x0 * m.w;
        o1.x += x1 * m.x; o1.y += x1 * m.y; o1.z += x1 * m.z; o1.w += x1 * m.w;
        o2.x += x2 * m.x; o2.y += x2 * m.y; o2.z += x2 * m.z; o2.w += x2 * m.w;
        o3.x += x3 * m.x; o3.y += x3 * m.y; o3.z += x3 * m.z; o3.w += x3 * m.w;
    }
    ELU4(o0) ELU4(o1) ELU4(o2) ELU4(o3)

    // gp1/gm1 scalars
    {
        float4 p = __ldg(&d_p4[ch]), q = __ldg(&d_q4[ch]);
        float pp0 = o0.x*p.x + o0.y*p.y + o0.z*p.z + o0.w*p.w;
        float pp1 = o1.x*p.x + o1.y*p.y + o1.z*p.z + o1.w*p.w;
        float pp2 = o2.x*p.x + o2.y*p.y + o2.z*p.z + o2.w*p.w;
        float pp3 = o3.x*p.x + o3.y*p.y + o3.z*p.z + o3.w*p.w;
        float qq0 = o0.x*q.x + o0.y*q.y + o0.z*q.z + o0.w*q.w;
        float qq1 = o1.x*q.x + o1.y*q.y + o1.z*q.z + o1.w*q.w;
        float qq2 = o2.x*q.x + o2.y*q.y + o2.z*q.z + o2.w*q.w;
        float qq3 = o3.x*q.x + o3.y*q.y + o3.z*q.z + o3.w*q.w;
        #pragma unroll
        for (int m = 8; m; m >>= 1) {
            pp0 += __shfl_xor_sync(0xffffffffu, pp0, m, 16);
            pp1 += __shfl_xor_sync(0xffffffffu, pp1, m, 16);
            pp2 += __shfl_xor_sync(0xffffffffu, pp2, m, 16);
            pp3 += __shfl_xor_sync(0xffffffffu, pp3, m, 16);
            qq0 += __shfl_xor_sync(0xffffffffu, qq0, m, 16);
            qq1 += __shfl_xor_sync(0xffffffffu, qq1, m, 16);
            qq2 += __shfl_xor_sync(0xffffffffu, qq2, m, 16);
            qq3 += __shfl_xor_sync(0xffffffffu, qq3, m, 16);
        }
        if (ch == 0) {
            if (nb0 + nl + 0 < NN) { d_gp1[nb0 + nl + 1] = pp0; d_gm1[nb0 + nl + 1] = qq0; }
            if (nb0 + nl + 1 < NN) { d_gp1[nb0 + nl + 2] = pp1; d_gm1[nb0 + nl + 2] = qq1; }
            if (nb0 + nl + 2 < NN) { d_gp1[nb0 + nl + 3] = pp2; d_gm1[nb0 + nl + 3] = qq2; }
            if (nb0 + nl + 3 < NN) { d_gp1[nb0 + nl + 4] = pp3; d_gm1[nb0 + nl + 4] = qq3; }
        }
    }

    // hp1 overwrite of own rows — half-warp private, warp sync suffices
    __syncwarp();
    *(float4*)&sacc[(nl + 0) * 68 + ch * 4] = o0;
    *(float4*)&sacc[(nl + 1) * 68 + ch * 4] = o1;
    *(float4*)&sacc[(nl + 2) * 68 + ch * 4] = o2;
    *(float4*)&sacc[(nl + 3) * 68 + ch * 4] = o3;
    __syncwarp();

    // ---- fused passes 2+3: th1 = hp1@Wg, tm1 = hp1@Wm ----
    float4 uA0 = make_float4(0.f,0.f,0.f,0.f), uA1 = uA0, uA2 = uA0, uA3 = uA0;
    float4 uB0 = uA0, uB1 = uA0, uB2 = uA0, uB3 = uA0;
    #pragma unroll
    for (int s4 = 0; s4 < 16; s4++) {
        float4 a0 = *(float4*)&sacc[(nl + 0) * 68 + s4 * 4];
        float4 a1 = *(float4*)&sacc[(nl + 1) * 68 + s4 * 4];
        float4 a2 = *(float4*)&sacc[(nl + 2) * 68 + s4 * 4];
        float4 a3 = *(float4*)&sacc[(nl + 3) * 68 + s4 * 4];
        {
            float4 w0 = sWg[(4 * s4 + 0) * 16 + ch];
            float4 w1 = sWg[(4 * s4 + 1) * 16 + ch];
            float4 w2 = sWg[(4 * s4 + 2) * 16 + ch];
            float4 w3 = sWg[(4 * s4 + 3) * 16 + ch];
            FMA4(uA0, a0, w0, w1, w2, w3)
            FMA4(uA1, a1, w0, w1, w2, w3)
            FMA4(uA2, a2, w0, w1, w2, w3)
            FMA4(uA3, a3, w0, w1, w2, w3)
        }
        {
            float4 w0 = sWm[(4 * s4 + 0) * 16 + ch];
            float4 w1 = sWm[(4 * s4 + 1) * 16 + ch];
            float4 w2 = sWm[(4 * s4 + 2) * 16 + ch];
            float4 w3 = sWm[(4 * s4 + 3) * 16 + ch];
            FMA4(uB0, a0, w0, w1, w2, w3)
            FMA4(uB1, a1, w0, w1, w2, w3)
            FMA4(uB2, a2, w0, w1, w2, w3)
            FMA4(uB3, a3, w0, w1, w2, w3)
        }
    }
    #pragma unroll
    for (int m = 0; m < 4; m++) {
        if (nb0 + nl + m >= NN) continue;
        float4 uA = (m == 0) ? uA0 : (m == 1) ? uA1 : (m == 2) ? uA2 : uA3;
        float4 uB = (m == 0) ? uB0 : (m == 1) ? uB1 : (m == 2) ? uB2 : uB3;
        uint2 pa, pb;
        pa.x = pack_half2(uA.x, uA.y); pa.y = pack_half2(uA.z, uA.w);
        pb.x = pack_half2(uB.x, uB.y); pb.y = pack_half2(uB.z, uB.w);
        d_th1h[(nb0 + nl + m + 1) * 16 + ch] = pa;
        d_tm1h[(nb0 + nl + m + 1) * 16 + ch] = pb;
    }

    if (blockIdx.x == 0 && t < 16) {
        d_th1h[t] = make_uint2(0u, 0u);
        d_tm1h[t] = make_uint2(0u, 0u);
    }
    if (blockIdx.x == 0 && t == 0) { d_gp1[0] = 0.f; d_gm1[0] = 0.f; }
}

// ---------------- fused alpha + gather + ELU, iteration 2 (fp16 tables) ----------
__global__ __launch_bounds__(256) void k_gather2(const int* __restrict__ se,
                                                 const int* __restrict__ bs,
                                                 const int* __restrict__ su,
                                                 const int* __restrict__ sul) {
    __shared__ float4 sbc[8][2][17];
    int t = threadIdx.x, w = t >> 5, l = t & 31, sub = l & 15, half = l >> 4;
    int n = (blockIdx.x * 8 + w) * 2 + half;

    int idx = se[n * KK + sub];
    int e   = bs[n * KK + sub];
    int j   = __ldg(&su[e]);
    float msk = (__ldg(&sul[e]) > 0) ? 1.f : 0.f;
    float v = __ldg(&d_gp1[idx]) + msk * __ldg(&d_gm1[j]);
    v = (v > 0.f) ? v : 0.2f * v;
    float alpha = softmax16((idx == 0) ? NEGINF : v);

    sbc[w][half][sub] = make_float4(alpha, __int_as_float(idx), __int_as_float(j),
                                    alpha * msk);
    __syncwarp();

    float4 acc = make_float4(0.f, 0.f, 0.f, 0.f);
    #pragma unroll
    for (int k = 0; k < KK; k++) {
        float4 b = sbc[w][half][k];
        int i  = __float_as_int(b.y);
        int jj = __float_as_int(b.z);
        uint2 hv = d_th1h[i * 16 + sub];
        float2 vA = unpack_half2(hv.x), vB = unpack_half2(hv.y);
        acc.x += b.x * vA.x; acc.y += b.x * vA.y;
        acc.z += b.x * vB.x; acc.w += b.x * vB.y;
        uint2 hu = d_tm1h[jj * 16 + sub];
        float2 uA = unpack_half2(hu.x), uB = unpack_half2(hu.y);
        acc.x += b.w * uA.x; acc.y += b.w * uA.y;
        acc.z += b.w * uB.x; acc.w += b.w * uB.y;
    }
    ELU4(acc)
    d_hp2v[(n + 1) * 16 + sub] = acc;
    if (blockIdx.x == 0 && t < 16) d_hp2v[t] = make_float4(0.f, 0.f, 0.f, 0.f);
}

// ---------------- readout ----------------------------------------------------------
__global__ __launch_bounds__(256) void k_out(const int* __restrict__ ls,
                                             float* __restrict__ out) {
    int wid = (blockIdx.x * blockDim.x + threadIdx.x) >> 5;
    int l = threadIdx.x & 31;
    int sub = l & 15;
    int mol = wid * 2 + (l >> 4);
    if (mol >= BBATCH) return;
    const int* row = ls + mol * MAXM;
    float4 acc = make_float4(0.f, 0.f, 0.f, 0.f);
    #pragma unroll 8
    for (int m = 0; m < MAXM; m++) {
        int i = __ldg(row + m);
        float4 v = d_hp2v[i * 16 + sub];
        acc.x += v.x; acc.y += v.y; acc.z += v.z; acc.w += v.w;
    }
    ((float4*)out)[mol * 16 + sub] = acc;
}

// ---------------- launch -----------------------------------------------------------
extern "C" void kernel_launch(void* const* d_in, const int* in_sizes, int n_in,
                              void* d_out, int out_size) {
    const float* tf  = (const float*)d_in[0];
    const float* fdg = (const float*)d_in[1];
    const float* rij = (const float*)d_in[2];
    const int*   se  = (const int*)d_in[3];
    const int*   bs  = (const int*)d_in[4];
    const int*   ls  = (const int*)d_in[5];
    const int*   su  = (const int*)d_in[6];
    const int*   sul = (const int*)d_in[7];
    const float* We  = (const float*)d_in[8];
    const float* be  = (const float*)d_in[9];
    const float* Wd  = (const float*)d_in[10];
    const float* bd  = (const float*)d_in[11];
    const float* Wg  = (const float*)d_in[12];
    const float* Wm  = (const float*)d_in[13];
    const float* ag  = (const float*)d_in[14];

    // sWg 16384 + sWm 16384 + sacc 17408 + sax 4352 = 54528 B
    int mega_smem = 2048 * 16 + 64 * 68 * 4 + 64 * 17 * 4;
    static int smem_set = 0;
    if (!smem_set) {
        cudaFuncSetAttribute(k_mega, cudaFuncAttributeMaxDynamicSharedMemorySize, mega_smem);
        smem_set = 1;
    }

    int gat_blocks = NN / 16;               // 3125
    int gemm_blocks = (NN + 63) / 64;       // 782

    k_consts<<<5, 256>>>(Wg, Wm, ag, Wd, bd, We, be);
    k_pre<<<NB_EMB + NB_ELOG, 256>>>(tf, We, be, fdg, rij);

    k_gather1<<<gat_blocks, 256>>>(se, bs, fdg, rij);
    k_mega<<<gemm_blocks, 256, mega_smem>>>(Wg, Wm);
    k_gather2<<<gat_blocks, 256>>>(se, bs, su, sul);

    k_out<<<(BBATCH / 2 + 7) / 8, 256>>>(ls, (float*)d_out);
}

// round 13
// speedup vs baseline: 1.2712x; 1.0326x over previous
#include <cuda_runtime.h>
#include <cuda_fp16.h>
#include <cstdint>
#include <math.h>

#define NN 50000
#define KK 16
#define EE 800000
#define BBATCH 1024
#define MAXM 48
#define FD 9
#define AD 10
#define HH 64
#define NEGINF (-1e9f)
#define NB_EMB 3126              // ceil((NN+1)/16)
#define NB_ELOG 3125             // EE/256

__device__ __forceinline__ unsigned pack_half2(float a, float b) {
    __half2 h = __floats2half2_rn(a, b);
    return *reinterpret_cast<unsigned*>(&h);
}
__device__ __forceinline__ float2 unpack_half2(unsigned u) {
    __half2 h = *reinterpret_cast<__half2*>(&u);
    return __half22float2(h);
}

// ---------------- scratch ------------------------------------------------------
__device__ uint2  d_hp0h[(NN + 1) * 16];   // fp16 node embeddings (row 0 = 0)
__device__ uint2  d_th1h[(NN + 1) * 16];   // fp16 hp1 @ Wg
__device__ uint2  d_tm1h[(NN + 1) * 16];   // fp16 hp1 @ Wm
__device__ uint2  d_hp2h[(NN + 1) * 16];   // fp16 hp2
__device__ float d_gp0[NN + 1];
__device__ float d_gp1[NN + 1];
__device__ float d_gm1[NN + 1];
__device__ float d_elog[EE];
__device__ uint2  d_accAh[NN * 16];        // fp16 aggregated neighbor feats
__device__ float d_accX16[NN * 16];
__device__ float4 d_p4[16];
__device__ float4 d_q4[16];
__device__ float d_qd[AD];
__device__ float d_c;
__device__ float d_wep[FD];      // We @ p
__device__ float d_c0;           // be . p
__device__ float4 d_M14[AD * 16];
__device__ float4 d_bm4[16];

// ---------------- constants (5 blocks: 0 = vectors, 1-4 = M14 slices) ------------
__global__ __launch_bounds__(256) void k_consts(const float* __restrict__ Wg,
                                                const float* __restrict__ Wm,
                                                const float* __restrict__ a,
                                                const float* __restrict__ Wd,
                                                const float* __restrict__ bd,
                                                const float* __restrict__ We,
                                                const float* __restrict__ be) {
    int t = threadIdx.x;
    if (blockIdx.x == 0) {
        __shared__ float sp[HH], sq[HH];
        if (t < HH) {
            float p = 0.f, q = 0.f;
            #pragma unroll 8
            for (int i = 0; i < HH; i++) {
                p += Wg[t * HH + i] * a[i];
                q += Wm[t * HH + i] * a[HH + i];
            }
            sp[t] = p; sq[t] = q;
            ((float*)d_p4)[t] = p;
            ((float*)d_q4)[t] = q;
        }
        __syncthreads();
        if (t < AD) {
            float s = 0.f;
            for (int i = 0; i < HH; i++) s += Wd[t * HH + i] * sq[i];
            d_qd[t] = s;
        } else if (t == AD) {
            float s = 0.f;
            for (int i = 0; i < HH; i++) s += bd[i] * sq[i];
            d_c = s;
        } else if (t >= 32 && t < 32 + FD) {
            int r = t - 32;
            float s = 0.f;
            for (int j = 0; j < HH; j++) s += We[r * HH + j] * sp[j];
            d_wep[r] = s;
        } else if (t == 32 + FD) {
            float s = 0.f;
            for (int j = 0; j < HH; j++) s += be[j] * sp[j];
            d_c0 = s;
        }
        if (t < HH) {
            float s = 0.f;
            for (int i = 0; i < HH; i++) s += bd[i] * Wm[i * HH + t];
            ((float*)d_bm4)[t] = s;
        }
    } else {
        int idx = (blockIdx.x - 1) * 160 + t;
        if (t < 160 && idx < AD * HH) {
            int r = idx >> 6, j = idx & 63;
            float s = 0.f;
            #pragma unroll 8
            for (int i = 0; i < HH; i++) s += Wd[r * HH + i] * Wm[i * HH + j];
            ((float*)d_M14)[idx] = s;
        }
    }
}

// ---------------- fused embed (+gp0, fp16 hp0) and per-edge logit ----------------
__global__ __launch_bounds__(256) void k_pre(const float* __restrict__ tf,
                                             const float* __restrict__ We,
                                             const float* __restrict__ be,
                                             const float* __restrict__ fdg,
                                             const float* __restrict__ rij) {
    int b = blockIdx.x;
    if (b < NB_EMB) {
        int t = threadIdx.x, w = t >> 5, l = t & 31, sub = l & 15, half = l >> 4;
        int row = b * 16 + w * 2 + half;
        if (row > NN) return;
        float4 acc = make_float4(0.f, 0.f, 0.f, 0.f);
        float g = 0.f;
        if (row > 0) {
            int n = row - 1;
            const float* r = tf + n * FD;
            acc = ((const float4*)be)[sub];
            g = d_c0;
            #pragma unroll
            for (int tt = 0; tt < FD; tt++) {
                float x = __ldg(r + tt);
                float4 ww = ((const float4*)We)[tt * 16 + sub];
                acc.x += x * ww.x; acc.y += x * ww.y; acc.z += x * ww.z; acc.w += x * ww.w;
                g += x * d_wep[tt];
            }
        }
        uint2 pk;
        pk.x = pack_half2(acc.x, acc.y);
        pk.y = pack_half2(acc.z, acc.w);
        d_hp0h[row * 16 + sub] = pk;
        if (sub == 0) d_gp0[row] = g;
    } else {
        int e = (b - NB_EMB) * 256 + threadIdx.x;
        if (e >= EE) return;
        float s = d_c + rij[e] * d_qd[9];
        const float* x = fdg + (long)e * FD;
        #pragma unroll
        for (int r = 0; r < FD; r++) s += x[r] * d_qd[r];
        d_elog[e] = s;
    }
}

// ---------------- softmax helper (width 16) --------------------------------------
__device__ __forceinline__ float softmax16(float logit) {
    float mx = logit;
    #pragma unroll
    for (int m = 8; m; m >>= 1) mx = fmaxf(mx, __shfl_xor_sync(0xffffffffu, mx, m, 16));
    float ex = __expf(logit - mx);
    float sum = ex;
    #pragma unroll
    for (int m = 8; m; m >>= 1) sum += __shfl_xor_sync(0xffffffffu, sum, m, 16);
    return ex / sum;
}

// ---------------- fused alpha + gather, iteration 1 (fp16 in, fp16 out) ----------
__global__ __launch_bounds__(256) void k_gather1(const int* __restrict__ se,
                                                 const int* __restrict__ bs,
                                                 const float* __restrict__ fdg,
                                                 const float* __restrict__ rij) {
    __shared__ float4 sbc[8][2][17];
    int t = threadIdx.x, w = t >> 5, l = t & 31, sub = l & 15, half = l >> 4;
    int n = (blockIdx.x * 8 + w) * 2 + half;     // < NN exactly

    int idx = se[n * KK + sub];
    int e   = bs[n * KK + sub];
    float v = __ldg(&d_gp0[idx]) + __ldg(&d_elog[e]);
    v = (v > 0.f) ? v : 0.2f * v;
    float alpha = softmax16((idx == 0) ? NEGINF : v);

    sbc[w][half][sub] = make_float4(alpha, __int_as_float(idx), __int_as_float(e), 0.f);
    __syncwarp();

    float4 acc = make_float4(0.f, 0.f, 0.f, 0.f);
    float ax = 0.f;
    #pragma unroll
    for (int k = 0; k < KK; k++) {
        float4 b = sbc[w][half][k];
        int i  = __float_as_int(b.y);
        int ee = __float_as_int(b.z);
        uint2 hv = d_hp0h[i * 16 + sub];
        float2 vA = unpack_half2(hv.x), vB = unpack_half2(hv.y);
        acc.x += b.x * vA.x; acc.y += b.x * vA.y;
        acc.z += b.x * vB.x; acc.w += b.x * vB.y;
        if (sub < AD) {
            float x = (sub < FD) ? fdg[(long)ee * FD + sub] : rij[ee];
            ax += b.x * x;
        }
    }
    uint2 pk;
    pk.x = pack_half2(acc.x, acc.y);
    pk.y = pack_half2(acc.z, acc.w);
    d_accAh[n * 16 + sub] = pk;
    d_accX16[n * 16 + sub] = ax;
}

#define FMA4(o, a, w0, w1, w2, w3)                                     \
    o.x += a.x * w0.x + a.y * w1.x + a.z * w2.x + a.w * w3.x;          \
    o.y += a.x * w0.y + a.y * w1.y + a.z * w2.y + a.w * w3.y;          \
    o.z += a.x * w0.z + a.y * w1.z + a.z * w2.z + a.w * w3.z;          \
    o.w += a.x * w0.w + a.y * w1.w + a.z * w2.w + a.w * w3.w;

#define ELU4(o) \
    o.x = (o.x > 0.f) ? o.x : expm1f(o.x); \
    o.y = (o.y > 0.f) ? o.y : expm1f(o.y); \
    o.z = (o.z > 0.f) ? o.z : expm1f(o.z); \
    o.w = (o.w > 0.f) ? o.w : expm1f(o.w);

// ---------------- mega GEMM: hp1 = ELU(accA@Wg + accX@M1 + bm);
//                  th1 = hp1@Wg; tm1 = hp1@Wm (fused, fp16 out); gp1/gm1 ---------
__global__ __launch_bounds__(256, 3) void k_mega(const float* __restrict__ Wg,
                                                 const float* __restrict__ Wm) {
    extern __shared__ float4 dyn[];
    float4* sWg = dyn;                       // 1024 float4
    float4* sWm = dyn + 1024;                // 1024 float4
    float*  sacc = (float*)(dyn + 2048);     // 64*68 floats (accA, then hp1)
    float*  sax  = sacc + 64 * 68;           // 64*17 floats

    int t = threadIdx.x;
    int nb0 = blockIdx.x * 64;
    for (int i = t; i < HH * 16; i += 256) {
        sWg[i] = ((const float4*)Wg)[i];
        sWm[i] = ((const float4*)Wm)[i];
    }
    for (int i = t; i < 1024; i += 256) {
        int node = i >> 4, s = i & 15, n = nb0 + node;
        float4 v = make_float4(0.f, 0.f, 0.f, 0.f);
        if (n < NN) {
            uint2 hv = d_accAh[n * 16 + s];
            float2 a = unpack_half2(hv.x), b = unpack_half2(hv.y);
            v = make_float4(a.x, a.y, b.x, b.y);
        }
        *(float4*)&sacc[node * 68 + s * 4] = v;
    }
    for (int i = t; i < 1024; i += 256) {
        int node = i >> 4, r = i & 15, n = nb0 + node;
        sax[node * 17 + r] = (n < NN) ? d_accX16[n * 16 + r] : 0.f;
    }
    __syncthreads();

    int ch = t & 15, g = t >> 4;
    int nl = g * 4;

    // ---- pass 1: hp1 = ELU(accA@Wg + accX@M1 + bm) ----
    float4 bm = __ldg(&d_bm4[ch]);
    float4 o0 = bm, o1 = bm, o2 = bm, o3 = bm;
    #pragma unroll
    for (int s4 = 0; s4 < 16; s4++) {
        float4 w0 = sWg[(4 * s4 + 0) * 16 + ch];
        float4 w1 = sWg[(4 * s4 + 1) * 16 + ch];
        float4 w2 = sWg[(4 * s4 + 2) * 16 + ch];
        float4 w3 = sWg[(4 * s4 + 3) * 16 + ch];
        float4 a0 = *(float4*)&sacc[(nl + 0) * 68 + s4 * 4];
        float4 a1 = *(float4*)&sacc[(nl + 1) * 68 + s4 * 4];
        float4 a2 = *(float4*)&sacc[(nl + 2) * 68 + s4 * 4];
        float4 a3 = *(float4*)&sacc[(nl + 3) * 68 + s4 * 4];
        FMA4(o0, a0, w0, w1, w2, w3)
        FMA4(o1, a1, w0, w1, w2, w3)
        FMA4(o2, a2, w0, w1, w2, w3)
        FMA4(o3, a3, w0, w1, w2, w3)
    }
    #pragma unroll
    for (int rr = 0; rr < AD; rr++) {
        float4 m = __ldg(&d_M14[rr * 16 + ch]);
        float x0 = sax[(nl + 0) * 17 + rr], x1 = sax[(nl + 1) * 17 + rr];
        float x2 = sax[(nl + 2) * 17 + rr], x3 = sax[(nl + 3) * 17 + rr];
        o0.x += x0 * m.x; o0.y += x0 * m.y; o0.z += x0 * m.z; o0.w += x0 * m.w;
        o1.x += x1 * m.x; o1.y += x1 * m.y; o1.z += x1 * m.z; o1.w += x1 * m.w;
        o2.x += x2 * m.x; o2.y += x2 * m.y; o2.z += x2 * m.z; o2.w += x2 * m.w;
        o3.x += x3 * m.x; o3.y += x3 * m.y; o3.z += x3 * m.z; o3.w += x3 * m.w;
    }
    ELU4(o0) ELU4(o1) ELU4(o2) ELU4(o3)

    // gp1/gm1 scalars
    {
        float4 p = __ldg(&d_p4[ch]), q = __ldg(&d_q4[ch]);
        float pp0 = o0.x*p.x + o0.y*p.y + o0.z*p.z + o0.w*p.w;
        float pp1 = o1.x*p.x + o1.y*p.y + o1.z*p.z + o1.w*p.w;
        float pp2 = o2.x*p.x + o2.y*p.y + o2.z*p.z + o2.w*p.w;
        float pp3 = o3.x*p.x + o3.y*p.y + o3.z*p.z + o3.w*p.w;
        float qq0 = o0.x*q.x + o0.y*q.y + o0.z*q.z + o0.w*q.w;
        float qq1 = o1.x*q.x + o1.y*q.y + o1.z*q.z + o1.w*q.w;
        float qq2 = o2.x*q.x + o2.y*q.y + o2.z*q.z + o2.w*q.w;
        float qq3 = o3.x*q.x + o3.y*q.y + o3.z*q.z + o3.w*q.w;
        #pragma unroll
        for (int m = 8; m; m >>= 1) {
            pp0 += __shfl_xor_sync(0xffffffffu, pp0, m, 16);
            pp1 += __shfl_xor_sync(0xffffffffu, pp1, m, 16);
            pp2 += __shfl_xor_sync(0xffffffffu, pp2, m, 16);
            pp3 += __shfl_xor_sync(0xffffffffu, pp3, m, 16);
            qq0 += __shfl_xor_sync(0xffffffffu, qq0, m, 16);
            qq1 += __shfl_xor_sync(0xffffffffu, qq1, m, 16);
            qq2 += __shfl_xor_sync(0xffffffffu, qq2, m, 16);
            qq3 += __shfl_xor_sync(0xffffffffu, qq3, m, 16);
        }
        if (ch == 0) {
            if (nb0 + nl + 0 < NN) { d_gp1[nb0 + nl + 1] = pp0; d_gm1[nb0 + nl + 1] = qq0; }
            if (nb0 + nl + 1 < NN) { d_gp1[nb0 + nl + 2] = pp1; d_gm1[nb0 + nl + 2] = qq1; }
            if (nb0 + nl + 2 < NN) { d_gp1[nb0 + nl + 3] = pp2; d_gm1[nb0 + nl + 3] = qq2; }
            if (nb0 + nl + 3 < NN) { d_gp1[nb0 + nl + 4] = pp3; d_gm1[nb0 + nl + 4] = qq3; }
        }
    }

    // hp1 overwrite of own rows — half-warp private, warp sync suffices
    __syncwarp();
    *(float4*)&sacc[(nl + 0) * 68 + ch * 4] = o0;
    *(float4*)&sacc[(nl + 1) * 68 + ch * 4] = o1;
    *(float4*)&sacc[(nl + 2) * 68 + ch * 4] = o2;
    *(float4*)&sacc[(nl + 3) * 68 + ch * 4] = o3;
    __syncwarp();

    // ---- fused passes 2+3: th1 = hp1@Wg, tm1 = hp1@Wm ----
    float4 uA0 = make_float4(0.f,0.f,0.f,0.f), uA1 = uA0, uA2 = uA0, uA3 = uA0;
    float4 uB0 = uA0, uB1 = uA0, uB2 = uA0, uB3 = uA0;
    #pragma unroll
    for (int s4 = 0; s4 < 16; s4++) {
        float4 a0 = *(float4*)&sacc[(nl + 0) * 68 + s4 * 4];
        float4 a1 = *(float4*)&sacc[(nl + 1) * 68 + s4 * 4];
        float4 a2 = *(float4*)&sacc[(nl + 2) * 68 + s4 * 4];
        float4 a3 = *(float4*)&sacc[(nl + 3) * 68 + s4 * 4];
        {
            float4 w0 = sWg[(4 * s4 + 0) * 16 + ch];
            float4 w1 = sWg[(4 * s4 + 1) * 16 + ch];
            float4 w2 = sWg[(4 * s4 + 2) * 16 + ch];
            float4 w3 = sWg[(4 * s4 + 3) * 16 + ch];
            FMA4(uA0, a0, w0, w1, w2, w3)
            FMA4(uA1, a1, w0, w1, w2, w3)
            FMA4(uA2, a2, w0, w1, w2, w3)
            FMA4(uA3, a3, w0, w1, w2, w3)
        }
        {
            float4 w0 = sWm[(4 * s4 + 0) * 16 + ch];
            float4 w1 = sWm[(4 * s4 + 1) * 16 + ch];
            float4 w2 = sWm[(4 * s4 + 2) * 16 + ch];
            float4 w3 = sWm[(4 * s4 + 3) * 16 + ch];
            FMA4(uB0, a0, w0, w1, w2, w3)
            FMA4(uB1, a1, w0, w1, w2, w3)
            FMA4(uB2, a2, w0, w1, w2, w3)
            FMA4(uB3, a3, w0, w1, w2, w3)
        }
    }
    #pragma unroll
    for (int m = 0; m < 4; m++) {
        if (nb0 + nl + m >= NN) continue;
        float4 uA = (m == 0) ? uA0 : (m == 1) ? uA1 : (m == 2) ? uA2 : uA3;
        float4 uB = (m == 0) ? uB0 : (m == 1) ? uB1 : (m == 2) ? uB2 : uB3;
        uint2 pa, pb;
        pa.x = pack_half2(uA.x, uA.y); pa.y = pack_half2(uA.z, uA.w);
        pb.x = pack_half2(uB.x, uB.y); pb.y = pack_half2(uB.z, uB.w);
        d_th1h[(nb0 + nl + m + 1) * 16 + ch] = pa;
        d_tm1h[(nb0 + nl + m + 1) * 16 + ch] = pb;
    }

    if (blockIdx.x == 0 && t < 16) {
        d_th1h[t] = make_uint2(0u, 0u);
        d_tm1h[t] = make_uint2(0u, 0u);
    }
    if (blockIdx.x == 0 && t == 0) { d_gp1[0] = 0.f; d_gm1[0] = 0.f; }
}

// ---------------- fused alpha + gather + ELU, iteration 2 (fp16 tables) ----------
__global__ __launch_bounds__(256) void k_gather2(const int* __restrict__ se,
                                                 const int* __restrict__ bs,
                                                 const int* __restrict__ su,
                                                 const int* __restrict__ sul) {
    __shared__ float4 sbc[8][2][17];
    int t = threadIdx.x, w = t >> 5, l = t & 31, sub = l & 15, half = l >> 4;
    int n = (blockIdx.x * 8 + w) * 2 + half;

    int idx = se[n * KK + sub];
    int e   = bs[n * KK + sub];
    int j   = __ldg(&su[e]);
    float msk = (__ldg(&sul[e]) > 0) ? 1.f : 0.f;
    float v = __ldg(&d_gp1[idx]) + msk * __ldg(&d_gm1[j]);
    v = (v > 0.f) ? v : 0.2f * v;
    float alpha = softmax16((idx == 0) ? NEGINF : v);

    sbc[w][half][sub] = make_float4(alpha, __int_as_float(idx), __int_as_float(j),
                                    alpha * msk);
    __syncwarp();

    float4 acc = make_float4(0.f, 0.f, 0.f, 0.f);
    #pragma unroll
    for (int k = 0; k < KK; k++) {
        float4 b = sbc[w][half][k];
        int i  = __float_as_int(b.y);
        int jj = __float_as_int(b.z);
        uint2 hv = d_th1h[i * 16 + sub];
        float2 vA = unpack_half2(hv.x), vB = unpack_half2(hv.y);
        acc.x += b.x * vA.x; acc.y += b.x * vA.y;
        acc.z += b.x * vB.x; acc.w += b.x * vB.y;
        uint2 hu = d_tm1h[jj * 16 + sub];
        float2 uA = unpack_half2(hu.x), uB = unpack_half2(hu.y);
        acc.x += b.w * uA.x; acc.y += b.w * uA.y;
        acc.z += b.w * uB.x; acc.w += b.w * uB.y;
    }
    ELU4(acc)
    uint2 pk;
    pk.x = pack_half2(acc.x, acc.y);
    pk.y = pack_half2(acc.z, acc.w);
    d_hp2h[(n + 1) * 16 + sub] = pk;
    if (blockIdx.x == 0 && t < 16) d_hp2h[t] = make_uint2(0u, 0u);
}

// ---------------- readout (fp16 hp2 -> fp32 out) ----------------------------------
__global__ __launch_bounds__(256) void k_out(const int* __restrict__ ls,
                                             float* __restrict__ out) {
    int wid = (blockIdx.x * blockDim.x + threadIdx.x) >> 5;
    int l = threadIdx.x & 31;
    int sub = l & 15;
    int mol = wid * 2 + (l >> 4);
    if (mol >= BBATCH) return;
    const int* row = ls + mol * MAXM;
    float4 acc = make_float4(0.f, 0.f, 0.f, 0.f);
    #pragma unroll 8
    for (int m = 0; m < MAXM; m++) {
        int i = __ldg(row + m);
        uint2 hv = d_hp2h[i * 16 + sub];
        float2 vA = unpack_half2(hv.x), vB = unpack_half2(hv.y);
        acc.x += vA.x; acc.y += vA.y; acc.z += vB.x; acc.w += vB.y;
    }
    ((float4*)out)[mol * 16 + sub] = acc;
}

// ---------------- launch -----------------------------------------------------------
extern "C" void kernel_launch(void* const* d_in, const int* in_sizes, int n_in,
                              void* d_out, int out_size) {
    const float* tf  = (const float*)d_in[0];
    const float* fdg = (const float*)d_in[1];
    const float* rij = (const float*)d_in[2];
    const int*   se  = (const int*)d_in[3];
    const int*   bs  = (const int*)d_in[4];
    const int*   ls  = (const int*)d_in[5];
    const int*   su  = (const int*)d_in[6];
    const int*   sul = (const int*)d_in[7];
    const float* We  = (const float*)d_in[8];
    const float* be  = (const float*)d_in[9];
    const float* Wd  = (const float*)d_in[10];
    const float* bd  = (const float*)d_in[11];
    const float* Wg  = (const float*)d_in[12];
    const float* Wm  = (const float*)d_in[13];
    const float* ag  = (const float*)d_in[14];

    // sWg 16384 + sWm 16384 + sacc 17408 + sax 4352 = 54528 B
    int mega_smem = 2048 * 16 + 64 * 68 * 4 + 64 * 17 * 4;
    static int smem_set = 0;
    if (!smem_set) {
        cudaFuncSetAttribute(k_mega, cudaFuncAttributeMaxDynamicSharedMemorySize, mega_smem);
        smem_set = 1;
    }

    int gat_blocks = NN / 16;               // 3125
    int gemm_blocks = (NN + 63) / 64;       // 782

    k_consts<<<5, 256>>>(Wg, Wm, ag, Wd, bd, We, be);
    k_pre<<<NB_EMB + NB_ELOG, 256>>>(tf, We, be, fdg, rij);

    k_gather1<<<gat_blocks, 256>>>(se, bs, fdg, rij);
    k_mega<<<gemm_blocks, 256, mega_smem>>>(Wg, Wm);
    k_gather2<<<gat_blocks, 256>>>(se, bs, su, sul);

    k_out<<<(BBATCH / 2 + 7) / 8, 256>>>(ls, (float*)d_out);
}